// round 2
// baseline (speedup 1.0000x reference)
#include <cuda_runtime.h>
#include <math.h>

#define GN     6
#define NCELL  36
#define HID    128
#define NT     128     // threads per block (pair kernel); 2 agents per thread
#define APB    (2*NT)  // agents per block = 256
#define SEG    16      // j-segments
#define TJ     512     // j tile size (== 8192/SEG)
#define MAXN   8192
#define BI     32      // rows per block in reduce+GEMM kernel

// Partial occupancy planes: [seg][cell][i]  (i contiguous -> coalesced, float4-able)
__device__ float g_part[SEG * NCELL * MAXN];

// ---- f32x2 packed helpers (sm_100+) -------------------------------------
__device__ __forceinline__ unsigned long long pack2(float lo, float hi) {
    unsigned long long r;
    asm("mov.b64 %0, {%1, %2};" : "=l"(r) : "f"(lo), "f"(hi));
    return r;
}
__device__ __forceinline__ void unpack2(unsigned long long v, float& lo, float& hi) {
    asm("mov.b64 {%0, %1}, %2;" : "=f"(lo), "=f"(hi) : "l"(v));
}
__device__ __forceinline__ unsigned long long add2(unsigned long long a, unsigned long long b) {
    unsigned long long r;
    asm("add.rn.f32x2 %0, %1, %2;" : "=l"(r) : "l"(a), "l"(b));
    return r;
}
__device__ __forceinline__ unsigned long long fma2(unsigned long long a, unsigned long long b,
                                                   unsigned long long c) {
    unsigned long long r;
    asm("fma.rn.f32x2 %0, %1, %2, %3;" : "=l"(r) : "l"(a), "l"(b), "l"(c));
    return r;
}

__global__ __launch_bounds__(NT)
void occ_pair_kernel(const float2* __restrict__ obs, int N) {
    __shared__ float2 tile[TJ];
    __shared__ int    occA[NCELL * NT];   // occ[cell*NT + tid]: bank = tid%32, conflict-free
    __shared__ int    occB[NCELL * NT];

    const int tid = threadIdx.x;
    const int iA  = blockIdx.x * APB + tid;
    const int iB  = iA + NT;
    const int seg = blockIdx.y;
    const int JS  = (N + SEG - 1) / SEG;
    const int j0  = seg * JS;
    const int j1  = min(j0 + JS, N);

    // Negated positions. Invalid agent (OOB or NaN) -> +1e30 so that
    // d = pj + n is huge for every bad combination (bad j uses +1e30 too):
    // F2I.FLOOR saturates -> unsigned range check excludes.
    float nxA = 1e30f, nyA = 1e30f, nxB = 1e30f, nyB = 1e30f;
    if (iA < N) {
        float2 p = obs[iA];
        if (!isnan(p.x) && !isnan(p.y)) { nxA = -p.x; nyA = -p.y; }
    }
    if (iB < N) {
        float2 p = obs[iB];
        if (!isnan(p.x) && !isnan(p.y)) { nxB = -p.x; nyB = -p.y; }
    }
    const unsigned long long nA = pack2(nxA, nyA);
    const unsigned long long nB = pack2(nxB, nyB);
    const unsigned long long TWO2   = pack2(2.0f, 2.0f);
    const unsigned long long THREE2 = pack2(3.0f, 3.0f);

    #pragma unroll
    for (int c = 0; c < NCELL; c++) { occA[c * NT + tid] = 0; occB[c * NT + tid] = 0; }
    __syncthreads();

    for (int jb = j0; jb < j1; jb += TJ) {
        const int nj = min(TJ, j1 - jb);
        for (int t = tid; t < nj; t += NT) {
            float2 p = obs[jb + t];
            if (isnan(p.x) || isnan(p.y)) { p.x = 1e30f; p.y = 1e30f; }
            tile[t] = p;
        }
        __syncthreads();

        #pragma unroll 8
        for (int jj = 0; jj < nj; jj++) {
            // broadcast LDS.64 (same addr all lanes)
            const unsigned long long pj = *reinterpret_cast<const unsigned long long*>(&tile[jj]);

            // Exact parity with reference per lane: d rounds once (add),
            // then RN(2*d + 3) == reference's (sub -> exact *2 -> add).
            {
                unsigned long long r2 = fma2(add2(pj, nA), TWO2, THREE2);
                float rx, ry; unpack2(r2, rx, ry);
                int ix = __float2int_rd(rx);
                int iy = __float2int_rd(ry);
                if ((unsigned)ix < (unsigned)GN && (unsigned)iy < (unsigned)GN)
                    occA[(ix * GN + iy) * NT + tid] += 1;
            }
            {
                unsigned long long r2 = fma2(add2(pj, nB), TWO2, THREE2);
                float rx, ry; unpack2(r2, rx, ry);
                int ix = __float2int_rd(rx);
                int iy = __float2int_rd(ry);
                if ((unsigned)ix < (unsigned)GN && (unsigned)iy < (unsigned)GN)
                    occB[(ix * GN + iy) * NT + tid] += 1;
            }
        }
        __syncthreads();
    }

    if (iA < N) {
        #pragma unroll
        for (int c = 0; c < NCELL; c++)
            g_part[(seg * NCELL + c) * N + iA] = (float)occA[c * NT + tid];
    }
    if (iB < N) {
        #pragma unroll
        for (int c = 0; c < NCELL; c++)
            g_part[(seg * NCELL + c) * N + iB] = (float)occB[c * NT + tid];
    }
}

// Fused partial-reduce + [N,36]x[36,128] GEMM. 256 threads, BI=32 rows/block.
__global__ __launch_bounds__(256)
void occ_gemm_kernel(const float2* __restrict__ obs,
                     const float*  __restrict__ W,
                     const float*  __restrict__ b,
                     float*        __restrict__ out, int N) {
    __shared__ float occ_s[NCELL][BI];
    const int tid = threadIdx.x;
    const int i0  = blockIdx.x * BI;

    // Phase 1: reduce SEG partial planes with float4 loads (high MLP, coalesced)
    for (int task = tid; task < NCELL * (BI / 4); task += 256) {
        const int c  = task >> 3;          // cell
        const int g4 = task & 7;           // which group of 4 rows
        const int i  = i0 + g4 * 4;
        float4 s = make_float4(0.f, 0.f, 0.f, 0.f);
        if (i + 3 < N) {
            #pragma unroll
            for (int sg = 0; sg < SEG; sg++) {
                const float4 v = *reinterpret_cast<const float4*>(
                    &g_part[(sg * NCELL + c) * N + i]);
                s.x += v.x; s.y += v.y; s.z += v.z; s.w += v.w;
            }
        }
        *reinterpret_cast<float4*>(&occ_s[c][g4 * 4]) = s;
    }

    // W row for this feature in registers
    const int h = tid & (HID - 1);
    float w[NCELL];
    #pragma unroll
    for (int c = 0; c < NCELL; c++) w[c] = W[h * NCELL + c];
    const float bias = b[h];
    __syncthreads();

    // Phase 2: each half of the block handles BI/2 rows; occ_s broadcast across lanes
    const int il0 = (tid >> 7) * (BI / 2);
    #pragma unroll
    for (int il2 = 0; il2 < BI / 2; il2++) {
        const int il = il0 + il2;
        const int i  = i0 + il;
        if (i >= N) break;
        float2 p = obs[i];
        float acc = bias;
        // Remove the self-pair (counted at cell 21 iff both coords finite)
        if (!isnan(p.x) && !isnan(p.y)) acc -= w[21];
        #pragma unroll
        for (int c = 0; c < NCELL; c++)
            acc = fmaf(occ_s[c][il], w[c], acc);
        out[i * HID + h] = acc;
    }
}

extern "C" void kernel_launch(void* const* d_in, const int* in_sizes, int n_in,
                              void* d_out, int out_size) {
    const float2* obs = (const float2*)d_in[0];
    const float*  W   = (const float*)d_in[1];
    const float*  b   = (const float*)d_in[2];
    float*        out = (float*)d_out;
    const int N = in_sizes[0] / 2;

    dim3 grid1((N + APB - 1) / APB, SEG);
    occ_pair_kernel<<<grid1, NT>>>(obs, N);
    occ_gemm_kernel<<<(N + BI - 1) / BI, 256>>>(obs, W, b, out, N);
}

// round 3
// speedup vs baseline: 1.2031x; 1.2031x over previous
#include <cuda_runtime.h>
#include <math.h>

#define GN     6
#define NCELL  36
#define HID    128
#define NT     128     // threads per block (pair kernel), 1 agent per thread
#define SEG    16      // j-segments
#define TJ     512     // j tile size (== 8192/SEG when N==MAXN)
#define MAXN   8192
#define BI     32      // rows per block in GEMM kernel

// Partial occupancy planes: [seg][cell][i]  (i contiguous -> coalesced float4)
__device__ float g_part[SEG * NCELL * MAXN];
// Reduced occupancy, transposed: [cell][i]
__device__ float g_occ[NCELL * MAXN];

// Branchless histogram bump: invalid pairs go to trash row NCELL.
__device__ __forceinline__ void bump(int* occ, int tid, float dx, float dy) {
    // dx = pj.x - pi.x rounds once (FADD by caller); RN(2*dx+3) == reference's
    // (sub -> exact *2 -> add), so floor boundaries are bit-identical.
    float rx = fmaf(dx, 2.0f, 3.0f);
    float ry = fmaf(dy, 2.0f, 3.0f);
    int ix = __float2int_rd(rx);     // huge sentinel -> saturate -> excluded
    int iy = __float2int_rd(ry);
    int cell = ix * GN + iy;
    bool ok = ((unsigned)ix < (unsigned)GN) & ((unsigned)iy < (unsigned)GN);
    cell = ok ? cell : NCELL;        // trash row, unconditional RMW (no branch)
    occ[cell * NT + tid] += 1;
}

template<bool EXACT>
__global__ __launch_bounds__(NT)
void occ_pair_kernel(const float2* __restrict__ obs, int N) {
    __shared__ __align__(16) float2 tile[TJ];
    __shared__ int occ[(NCELL + 1) * NT];   // +1 trash row; bank = tid%32, conflict-free

    const int tid = threadIdx.x;
    const int i   = blockIdx.x * NT + tid;
    const int seg = blockIdx.y;
    const int JS  = EXACT ? (MAXN / SEG) : ((N + SEG - 1) / SEG);
    const int j0  = seg * JS;
    const int j1  = EXACT ? (j0 + JS) : min(j0 + JS, N);

    // Negated position. Invalid agent (OOB or any NaN coord) -> +1e30 so every
    // bad combination gives dx ~ +1e30..2e30 -> F2I saturates -> trash row.
    float nx = 1e30f, ny = 1e30f;
    if (i < N) {
        float2 p = obs[i];
        if (!isnan(p.x) && !isnan(p.y)) { nx = -p.x; ny = -p.y; }
    }

    #pragma unroll
    for (int c = 0; c <= NCELL; c++) occ[c * NT + tid] = 0;
    __syncthreads();

    for (int jb = j0; jb < j1; jb += TJ) {
        const int nj = EXACT ? TJ : min(TJ, j1 - jb);
        for (int t = tid; t < nj; t += NT) {
            float2 p = obs[jb + t];
            if (isnan(p.x) || isnan(p.y)) { p.x = 1e30f; p.y = 1e30f; }
            tile[t] = p;
        }
        __syncthreads();

        // Two pairs per LDS.128 broadcast.
        const float4* t4 = (const float4*)tile;
        const int nj2 = nj >> 1;
        #pragma unroll 8
        for (int jj = 0; jj < nj2; jj++) {
            const float4 q = t4[jj];
            bump(occ, tid, q.x + nx, q.y + ny);
            bump(occ, tid, q.z + nx, q.w + ny);
        }
        if (!EXACT && (nj & 1)) {
            const float2 p = tile[nj - 1];
            bump(occ, tid, p.x + nx, p.y + ny);
        }
        __syncthreads();
    }

    if (i < N) {
        #pragma unroll
        for (int c = 0; c < NCELL; c++)
            g_part[(seg * NCELL + c) * N + i] = (float)occ[c * NT + tid];
    }
}

// Massively parallel segment reduction: one thread per (cell, 4 agents).
__global__ __launch_bounds__(256)
void occ_reduce_kernel(int N) {
    const int nI4 = (N + 3) >> 2;
    const int t   = blockIdx.x * 256 + threadIdx.x;
    if (t >= NCELL * nI4) return;
    const int c = t / nI4;
    const int i = (t - c * nI4) * 4;

    if (((N & 3) == 0) & (i + 3 < N)) {
        float4 s = make_float4(0.f, 0.f, 0.f, 0.f);
        #pragma unroll
        for (int sg = 0; sg < SEG; sg++) {
            const float4 v = *reinterpret_cast<const float4*>(
                &g_part[(sg * NCELL + c) * N + i]);
            s.x += v.x; s.y += v.y; s.z += v.z; s.w += v.w;
        }
        *reinterpret_cast<float4*>(&g_occ[c * N + i]) = s;
    } else {
        for (int k = 0; k < 4 && i + k < N; k++) {
            float s = 0.f;
            #pragma unroll
            for (int sg = 0; sg < SEG; sg++)
                s += g_part[(sg * NCELL + c) * N + i + k];
            g_occ[c * N + i + k] = s;
        }
    }
}

// [N,36] x [36,128] GEMM with smem-staged W (coalesced) and broadcast occ reads.
__global__ __launch_bounds__(256)
void occ_gemm_kernel(const float2* __restrict__ obs,
                     const float*  __restrict__ W,
                     const float*  __restrict__ b,
                     float*        __restrict__ out, int N) {
    __shared__ float sW[HID * 37];                   // stride 37: (5h+c)%32 conflict-free
    __shared__ __align__(16) float occ_s[BI][40];    // row stride 40: float4-aligned
    __shared__ float sself[BI];

    const int tid = threadIdx.x;
    const int i0  = blockIdx.x * BI;

    // Stage W coalesced (one pass over 4608 floats).
    for (int idx = tid; idx < HID * NCELL; idx += 256) {
        const int h = idx / NCELL;
        sW[h * 37 + (idx - h * NCELL)] = W[idx];
    }
    // Load occ tile (coalesced along i from the [cell][i] layout).
    for (int idx = tid; idx < NCELL * BI; idx += 256) {
        const int c = idx >> 5, l = idx & 31;
        const int i = i0 + l;
        occ_s[l][c] = (i < N) ? g_occ[c * N + i] : 0.f;
    }
    #pragma unroll
    for (int idx = tid; idx < BI; idx += 256) { } // (no-op keeps structure clear)
    if (tid < BI) {
        const int i = i0 + tid;
        float v = 0.f;
        if (i < N) {
            const float2 p = obs[i];
            if (!isnan(p.x) && !isnan(p.y)) v = 1.f;
        }
        sself[tid] = v;
    }
    __syncthreads();

    const int h = tid & (HID - 1);
    float w[NCELL];
    #pragma unroll
    for (int c = 0; c < NCELL; c++) w[c] = sW[h * 37 + c];
    const float bias = b[h];

    const int il0 = (tid >> 7) * (BI / 2);
    #pragma unroll
    for (int r = 0; r < BI / 2; r++) {
        const int il = il0 + r;
        const int i  = i0 + il;
        if (i >= N) break;
        // Self-pair was counted at cell 21 iff agent i is finite; remove it.
        float acc = fmaf(-sself[il], w[21], bias);
        const float4* row = (const float4*)&occ_s[il][0];
        #pragma unroll
        for (int c4 = 0; c4 < 9; c4++) {
            const float4 v = row[c4];     // broadcast LDS.128
            acc = fmaf(v.x, w[c4 * 4 + 0], acc);
            acc = fmaf(v.y, w[c4 * 4 + 1], acc);
            acc = fmaf(v.z, w[c4 * 4 + 2], acc);
            acc = fmaf(v.w, w[c4 * 4 + 3], acc);
        }
        out[i * HID + h] = acc;
    }
}

extern "C" void kernel_launch(void* const* d_in, const int* in_sizes, int n_in,
                              void* d_out, int out_size) {
    const float2* obs = (const float2*)d_in[0];
    const float*  W   = (const float*)d_in[1];
    const float*  b   = (const float*)d_in[2];
    float*        out = (float*)d_out;
    const int N = in_sizes[0] / 2;

    if (N == MAXN) {
        dim3 g1(MAXN / NT, SEG);
        occ_pair_kernel<true><<<g1, NT>>>(obs, N);
    } else {
        dim3 g1((N + NT - 1) / NT, SEG);
        occ_pair_kernel<false><<<g1, NT>>>(obs, N);
    }
    const int nI4 = (N + 3) >> 2;
    const int rthreads = NCELL * nI4;
    occ_reduce_kernel<<<(rthreads + 255) / 256, 256>>>(N);
    occ_gemm_kernel<<<(N + BI - 1) / BI, 256>>>(obs, W, b, out, N);
}

// round 4
// speedup vs baseline: 1.2037x; 1.0005x over previous
#include <cuda_runtime.h>
#include <math.h>

#define GN     6
#define NCELL  36
#define HID    128
#define NT     64      // threads per block (pair kernel), 1 agent per thread
#define SEG    16      // j-segments
#define TJ     512     // j tile size (== 8192/SEG when N==MAXN)
#define MAXN   8192
#define BI     32      // rows per block in fused epilogue kernel

// Partial occupancy planes: [seg][cell][i]  (i contiguous -> coalesced float4)
__device__ float g_part[SEG * NCELL * MAXN];

// Branchless histogram bump: invalid pairs go to trash row NCELL.
__device__ __forceinline__ void bump(int* occ, int tid, float dx, float dy) {
    // dx = pj.x - pi.x rounds once (FADD by caller); RN(2*dx+3) == reference's
    // (sub -> exact *2 -> add), so floor boundaries are bit-identical.
    float rx = fmaf(dx, 2.0f, 3.0f);
    float ry = fmaf(dy, 2.0f, 3.0f);
    int ix = __float2int_rd(rx);     // huge sentinel -> saturate -> excluded
    int iy = __float2int_rd(ry);
    int cell = ix * GN + iy;
    bool ok = ((unsigned)ix < (unsigned)GN) & ((unsigned)iy < (unsigned)GN);
    cell = ok ? cell : NCELL;        // trash row, unconditional RMW (no branch)
    occ[cell * NT + tid] += 1;
}

template<bool EXACT>
__global__ __launch_bounds__(NT)
void occ_pair_kernel(const float2* __restrict__ obs, int N) {
    __shared__ __align__(16) float2 tile[TJ];
    __shared__ int occ[(NCELL + 1) * NT];   // +1 trash row; bank = tid%32, conflict-free

    const int tid = threadIdx.x;
    const int i   = blockIdx.x * NT + tid;
    const int seg = blockIdx.y;
    const int JS  = EXACT ? (MAXN / SEG) : ((N + SEG - 1) / SEG);
    const int j0  = seg * JS;
    const int j1  = EXACT ? (j0 + JS) : min(j0 + JS, N);

    // Negated position. Invalid agent (OOB or any NaN coord) -> +1e30 so every
    // bad combination gives dx ~ +1e30..2e30 -> F2I saturates -> trash row.
    float nx = 1e30f, ny = 1e30f;
    if (i < N) {
        float2 p = obs[i];
        if (!isnan(p.x) && !isnan(p.y)) { nx = -p.x; ny = -p.y; }
    }

    #pragma unroll
    for (int c = 0; c <= NCELL; c++) occ[c * NT + tid] = 0;
    __syncthreads();

    for (int jb = j0; jb < j1; jb += TJ) {
        const int nj = EXACT ? TJ : min(TJ, j1 - jb);
        for (int t = tid; t < nj; t += NT) {
            float2 p = obs[jb + t];
            if (isnan(p.x) || isnan(p.y)) { p.x = 1e30f; p.y = 1e30f; }
            tile[t] = p;
        }
        __syncthreads();

        // Two pairs per LDS.128 broadcast.
        const float4* t4 = (const float4*)tile;
        const int nj2 = nj >> 1;
        #pragma unroll 8
        for (int jj = 0; jj < nj2; jj++) {
            const float4 q = t4[jj];
            bump(occ, tid, q.x + nx, q.y + ny);
            bump(occ, tid, q.z + nx, q.w + ny);
        }
        if (!EXACT && (nj & 1)) {
            const float2 p = tile[nj - 1];
            bump(occ, tid, p.x + nx, p.y + ny);
        }
        __syncthreads();
    }

    if (i < N) {
        #pragma unroll
        for (int c = 0; c < NCELL; c++)
            g_part[(seg * NCELL + c) * N + i] = (float)occ[c * NT + tid];
    }
}

// Fused: segment-reduce g_part into smem, then [BI,36] x [36,128] GEMM.
__global__ __launch_bounds__(256)
void occ_gemm_kernel(const float2* __restrict__ obs,
                     const float*  __restrict__ W,
                     const float*  __restrict__ b,
                     float*        __restrict__ out, int N) {
    __shared__ float sW[HID * 37];                   // stride 37: (5h+c)%32 conflict-free
    __shared__ __align__(16) float occ_s[BI][40];    // row stride 40: float4-aligned
    __shared__ float sself[BI];

    const int tid = threadIdx.x;
    const int i0  = blockIdx.x * BI;

    // Stage W coalesced (one pass over 4608 floats).
    for (int idx = tid; idx < HID * NCELL; idx += 256) {
        const int h = idx / NCELL;
        sW[h * 37 + (idx - h * NCELL)] = W[idx];
    }

    // Phase 1: reduce SEG partial planes. Tasks: (cell, group-of-4-rows).
    for (int task = tid; task < NCELL * (BI / 4); task += 256) {
        const int c  = task >> 3;
        const int g4 = task & 7;
        const int i  = i0 + g4 * 4;
        float4 s = make_float4(0.f, 0.f, 0.f, 0.f);
        if (((N & 3) == 0) && (i + 3 < N)) {
            #pragma unroll
            for (int sg = 0; sg < SEG; sg++) {
                const float4 v = *reinterpret_cast<const float4*>(
                    &g_part[(sg * NCELL + c) * N + i]);
                s.x += v.x; s.y += v.y; s.z += v.z; s.w += v.w;
            }
        } else {
            float t[4] = {0.f, 0.f, 0.f, 0.f};
            for (int k = 0; k < 4 && i + k < N; k++)
                for (int sg = 0; sg < SEG; sg++)
                    t[k] += g_part[(sg * NCELL + c) * N + i + k];
            s.x = t[0]; s.y = t[1]; s.z = t[2]; s.w = t[3];
        }
        occ_s[g4 * 4 + 0][c] = s.x;
        occ_s[g4 * 4 + 1][c] = s.y;
        occ_s[g4 * 4 + 2][c] = s.z;
        occ_s[g4 * 4 + 3][c] = s.w;
    }
    if (tid < BI) {
        const int i = i0 + tid;
        float v = 0.f;
        if (i < N) {
            const float2 p = obs[i];
            if (!isnan(p.x) && !isnan(p.y)) v = 1.f;
        }
        sself[tid] = v;
    }
    __syncthreads();

    // Phase 2: GEMM. Each half-block handles BI/2 rows; occ_s broadcast per warp.
    const int h = tid & (HID - 1);
    float w[NCELL];
    #pragma unroll
    for (int c = 0; c < NCELL; c++) w[c] = sW[h * 37 + c];
    const float bias = b[h];

    const int il0 = (tid >> 7) * (BI / 2);
    #pragma unroll
    for (int r = 0; r < BI / 2; r++) {
        const int il = il0 + r;
        const int i  = i0 + il;
        if (i >= N) break;
        // Self-pair was counted at cell 21 iff agent i is finite; remove it.
        float acc = fmaf(-sself[il], w[21], bias);
        const float4* row = (const float4*)&occ_s[il][0];
        #pragma unroll
        for (int c4 = 0; c4 < 9; c4++) {
            const float4 v = row[c4];     // broadcast LDS.128
            acc = fmaf(v.x, w[c4 * 4 + 0], acc);
            acc = fmaf(v.y, w[c4 * 4 + 1], acc);
            acc = fmaf(v.z, w[c4 * 4 + 2], acc);
            acc = fmaf(v.w, w[c4 * 4 + 3], acc);
        }
        out[i * HID + h] = acc;
    }
}

extern "C" void kernel_launch(void* const* d_in, const int* in_sizes, int n_in,
                              void* d_out, int out_size) {
    const float2* obs = (const float2*)d_in[0];
    const float*  W   = (const float*)d_in[1];
    const float*  b   = (const float*)d_in[2];
    float*        out = (float*)d_out;
    const int N = in_sizes[0] / 2;

    if (N == MAXN) {
        dim3 g1(MAXN / NT, SEG);
        occ_pair_kernel<true><<<g1, NT>>>(obs, N);
    } else {
        dim3 g1((N + NT - 1) / NT, SEG);
        occ_pair_kernel<false><<<g1, NT>>>(obs, N);
    }
    occ_gemm_kernel<<<(N + BI - 1) / BI, 256>>>(obs, W, b, out, N);
}